// round 7
// baseline (speedup 1.0000x reference)
#include <cuda_runtime.h>
#include <cuda_bf16.h>

typedef unsigned long long ull;

#define NB   256
#define AUGP 146     // smem aug row stride (146 cols: 145 + 1 zero pad)
#define CH   145
#define SIGK 21170
#define SIGS 21184

__device__ float g_sig[NB * SIGS];

__device__ __forceinline__ ull pack2(float lo, float hi) {
    ull r; asm("mov.b64 %0, {%1, %2};" : "=l"(r) : "f"(lo), "f"(hi)); return r;
}
__device__ __forceinline__ void unpack2(ull v, float& lo, float& hi) {
    asm("mov.b64 {%0, %1}, %2;" : "=f"(lo), "=f"(hi) : "l"(v));
}
__device__ __forceinline__ void ffma2(ull& acc, ull a, ull b) {
    asm("fma.rn.f32x2 %0, %1, %2, %0;" : "+l"(acc) : "l"(a), "l"(b));
}

// smem layout (floats)
#define O_AUG  0
#define O_W1   37084            // 48*64
#define O_W2   40156            // 64*128
#define O_H    48348            // 32*66
#define O_B1   50460
#define O_B2   50524
#define O_X01  50652            // x[0],x[1] (32)
#define O_D    50684            // 2*8*152
#define O_U    53116            // 2*8*160
#define O_A0   55676            // 160
#define SMEMF  55836            // *4 = 223344 bytes

// ============================================================
// Fused: conv1+conv2 -> aug (smem) -> depth-2 signature -> g_sig
// one CTA (512 thr) per n
// ============================================================
__global__ __launch_bounds__(512, 1) void k_fused(
    const float* __restrict__ q,
    const float* __restrict__ w1, const float* __restrict__ b1,
    const float* __restrict__ w2, const float* __restrict__ b2)
{
    extern __shared__ float sm[];
    float* sAug = sm + O_AUG;
    float* sW1  = sm + O_W1;
    float* sW2  = sm + O_W2;
    float* sH   = sm + O_H;
    float* sB1  = sm + O_B1;
    float* sB2  = sm + O_B2;
    float* sX01 = sm + O_X01;
    float* sA0  = sm + O_A0;

    int n = blockIdx.x, tid = threadIdx.x;
    int b = n >> 3, hh = n & 7;

    // ---- load inputs ----
    for (int idx = tid; idx < 254 * 16; idx += 512) {
        int t = idx >> 4, e = idx & 15;
        sAug[t * AUGP + e] = q[(((size_t)b * 256 + t + 2) * 8 + hh) * 16 + e];
    }
    if (tid < 32)
        sX01[tid] = q[(((size_t)b * 256 + (tid >> 4)) * 8 + hh) * 16 + (tid & 15)];
    for (int t = tid; t < 254; t += 512) {
        sAug[t * AUGP + 16]  = (float)t * (1.0f / 253.0f);  // time channel
        sAug[t * AUGP + 145] = 0.f;                          // pad col
    }
    for (int idx = tid; idx < 3072; idx += 512) sW1[idx] = w1[idx];
    for (int idx = tid; idx < 8192; idx += 512) sW2[idx] = w2[idx];
    if (tid < 64) sB1[tid] = b1[tid];
    else if (tid < 192) sB2[tid - 64] = b2[tid - 64];
    __syncthreads();

    // ---- conv1 + conv2 per 32-t chunk ----
    int t_loc = tid >> 4;
    int mp = tid & 15;       // conv1 m-pair base
    int cp = tid & 15;       // conv2 c-pair base
    for (int c0 = 0; c0 < 254; c0 += 32) {
        int tcnt = min(32, 254 - c0);
        // conv1: out[tt][m], m-pairs (mp+16j)
        if (t_loc < tcnt) {
            int tt = c0 + t_loc;
            const float* xr0 = (tt >= 2) ? &sAug[(tt - 2) * AUGP] : &sX01[tt * 16];
            const float* xr1 = (tt >= 1) ? &sAug[(tt - 1) * AUGP] : &sX01[16];
            const float* xr2 = &sAug[tt * AUGP];
            ull a1[2];
            #pragma unroll
            for (int j = 0; j < 2; j++)
                a1[j] = pack2(sB1[2 * (mp + 16 * j)], sB1[2 * (mp + 16 * j) + 1]);
            const float* xr[3] = {xr0, xr1, xr2};
            #pragma unroll
            for (int w = 0; w < 3; w++) {
                #pragma unroll
                for (int e = 0; e < 16; e++) {
                    float xv = xr[w][e];
                    ull xp = pack2(xv, xv);
                    #pragma unroll
                    for (int j = 0; j < 2; j++)
                        ffma2(a1[j], xp, *(const ull*)&sW1[(w * 16 + e) * 64 + 2 * (mp + 16 * j)]);
                }
            }
            #pragma unroll
            for (int j = 0; j < 2; j++)
                *(ull*)&sH[t_loc * 66 + 2 * (mp + 16 * j)] = a1[j];
        }
        __syncthreads();
        // conv2 + relu -> aug cols 17..144
        if (t_loc < tcnt) {
            ull a2[4];
            #pragma unroll
            for (int j = 0; j < 4; j++)
                a2[j] = pack2(sB2[2 * (cp + 16 * j)], sB2[2 * (cp + 16 * j) + 1]);
            const float* hr = &sH[t_loc * 66];
            #pragma unroll
            for (int m = 0; m < 64; m++) {
                float h = hr[m];
                ull hp = pack2(h, h);
                #pragma unroll
                for (int j = 0; j < 4; j++)
                    ffma2(a2[j], hp, *(const ull*)&sW2[m * 128 + 2 * (cp + 16 * j)]);
            }
            float* ar = &sAug[(c0 + t_loc) * AUGP + 17];
            #pragma unroll
            for (int j = 0; j < 4; j++) {
                float lo, hi; unpack2(a2[j], lo, hi);
                int c = 2 * (cp + 16 * j);
                ar[c]     = fmaxf(lo, 0.f);
                ar[c + 1] = fmaxf(hi, 0.f);
            }
        }
        __syncthreads();
    }

    // ---- s1, pads, sA0 ----
    float* sig = g_sig + (size_t)n * SIGS;
    if (tid < CH) sig[tid] = sAug[253 * AUGP + tid] - sAug[tid];
    if (tid >= 160 && tid < 160 + (SIGS - SIGK)) sig[SIGK + (tid - 160)] = 0.f;
    if (tid < 160) sA0[tid] = (tid < CH) ? sAug[tid] : 0.f;
    __syncthreads();

    // ---- signature main loop: 32 tiles of 8 t-steps, double buffered ----
    float* sD = sm + O_D;    // [2][8][152]
    float* sU = sm + O_U;    // [2][8][160]
    int kk = tid >> 6;       // 0..7
    int cb = tid & 63;

    // fill tile 0
    {
        int t = kk;
        #pragma unroll
        for (int ci = 0; ci < 3; ci++) {
            int cc = cb + 64 * ci;
            float a0v = 0.f, a1v = 0.f;
            bool in = (cc < AUGP);   // t < 253 always for tile 0
            if (in) { a0v = sAug[t * AUGP + cc]; a1v = sAug[(t + 1) * AUGP + cc]; }
            if (cc < 152) sD[kk * 152 + cc] = a1v - a0v;
            if (cc < 160) sU[kk * 160 + cc] = in ? (0.5f * (a0v + a1v) - sA0[cc]) : 0.f;
        }
    }
    __syncthreads();

    int ty = tid >> 4, tx = tid & 15;   // rows ty+32r, col-pairs tx+16s
    ull acc[5][5];
    #pragma unroll
    for (int r = 0; r < 5; r++)
        #pragma unroll
        for (int s = 0; s < 5; s++) acc[r][s] = 0ull;

    for (int it = 0; it < 32; it++) {
        int cur = it & 1;
        const float* dD = sD + cur * (8 * 152);
        const float* dU = sU + cur * (8 * 160);
        #pragma unroll
        for (int k2 = 0; k2 < 8; k2++) {
            ull d2[5];
            #pragma unroll
            for (int s = 0; s < 5; s++)
                d2[s] = *(const ull*)&dD[k2 * 152 + 2 * (tx + 16 * s)];
            #pragma unroll
            for (int r = 0; r < 5; r++) {
                float u = dU[k2 * 160 + ty + 32 * r];
                ull uu = pack2(u, u);
                #pragma unroll
                for (int s = 0; s < 5; s++) ffma2(acc[r][s], uu, d2[s]);
            }
        }
        if (it + 1 < 32) {
            int nxt = cur ^ 1;
            float* nD = sD + nxt * (8 * 152);
            float* nU = sU + nxt * (8 * 160);
            int t = 8 * (it + 1) + kk;
            bool tok = (t < 253);
            #pragma unroll
            for (int ci = 0; ci < 3; ci++) {
                int cc = cb + 64 * ci;
                float a0v = 0.f, a1v = 0.f;
                bool in = tok && (cc < AUGP);
                if (in) { a0v = sAug[t * AUGP + cc]; a1v = sAug[(t + 1) * AUGP + cc]; }
                if (cc < 152) nD[kk * 152 + cc] = a1v - a0v;
                if (cc < 160) nU[kk * 160 + cc] = in ? (0.5f * (a0v + a1v) - sA0[cc]) : 0.f;
            }
        }
        __syncthreads();
    }

    // ---- epilogue: write S ----
    #pragma unroll
    for (int r = 0; r < 5; r++) {
        int i = ty + 32 * r;
        if (i >= CH) continue;
        float* row = sig + 145 + i * 145;
        #pragma unroll
        for (int s = 0; s < 5; s++) {
            int j = 2 * (tx + 16 * s);
            float lo, hi; unpack2(acc[r][s], lo, hi);
            if (j < CH)     row[j]     = lo;
            if (j + 1 < CH) row[j + 1] = hi;
        }
    }
}

// ============================================================
// K3a: init out with bias
// ============================================================
__global__ void k_bias(const float* __restrict__ lb, float* __restrict__ out)
{
    int i = blockIdx.x * 256 + threadIdx.x;
    out[i] = lb[i & 255];
}

// ============================================================
// K3b: split-K GEMM, double-buffered (unchanged)
// ============================================================
#define SPLITK 72
#define KCH    296

__global__ __launch_bounds__(256, 2) void k_gemm(
    const float* __restrict__ W, float* __restrict__ out)
{
    __shared__ float sAd[2][8][264];
    __shared__ float sB[2][8][132];

    int n0 = blockIdx.x * 128, o0 = blockIdx.y * 128;
    int kb = blockIdx.z * KCH;
    int kend = min(kb + KCH, SIGS);
    int nk = (kend - kb) >> 3;
    int tid = threadIdx.x, ty = tid >> 4, tx = tid & 15;

    int am = tid >> 1;
    int ak = (tid & 1) * 4;
    int bk = tid >> 5;
    int bo = (tid & 31) * 4;

    const float* aptr = &g_sig[(size_t)(n0 + am) * SIGS + ak];
    const float* bptr = &W[(size_t)bk * 256 + o0 + bo];

    ull acc[8][4];
    #pragma unroll
    for (int i = 0; i < 8; i++)
        #pragma unroll
        for (int j = 0; j < 4; j++) acc[i][j] = 0ull;

    float4 av = *(const float4*)(aptr + kb);
    float4 bv = make_float4(0.f, 0.f, 0.f, 0.f);
    if (kb + bk < SIGK) bv = *(const float4*)(bptr + (size_t)kb * 256);
    {
        float* d = &sAd[0][ak][2 * am];
        d[0] = av.x; d[1] = av.x; d += 264; d[0] = av.y; d[1] = av.y;
        d += 264; d[0] = av.z; d[1] = av.z; d += 264; d[0] = av.w; d[1] = av.w;
        *(float4*)&sB[0][bk][bo] = bv;
    }

    for (int it = 0; it < nk; it++) {
        int cur = it & 1;
        float4 av2, bv2;
        if (it + 1 < nk) {
            int k0 = kb + 8 * (it + 1);
            av2 = *(const float4*)(aptr + k0);
            bv2 = make_float4(0.f, 0.f, 0.f, 0.f);
            if (k0 + bk < SIGK) bv2 = *(const float4*)(bptr + (size_t)k0 * 256);
        }
        __syncthreads();
        #pragma unroll
        for (int kk = 0; kk < 8; kk++) {
            const float* arow = &sAd[cur][kk][16 * ty];
            ull a[8];
            #pragma unroll
            for (int i = 0; i < 8; i++) a[i] = *(const ull*)(arow + 2 * i);
            ulonglong2 bl = *(const ulonglong2*)&sB[cur][kk][4 * tx];
            ulonglong2 bh = *(const ulonglong2*)&sB[cur][kk][64 + 4 * tx];
            #pragma unroll
            for (int i = 0; i < 8; i++) {
                ffma2(acc[i][0], a[i], bl.x);
                ffma2(acc[i][1], a[i], bl.y);
                ffma2(acc[i][2], a[i], bh.x);
                ffma2(acc[i][3], a[i], bh.y);
            }
        }
        if (it + 1 < nk) {
            int nxt = cur ^ 1;
            float* d = &sAd[nxt][ak][2 * am];
            d[0] = av2.x; d[1] = av2.x; d += 264; d[0] = av2.y; d[1] = av2.y;
            d += 264; d[0] = av2.z; d[1] = av2.z; d += 264; d[0] = av2.w; d[1] = av2.w;
            *(float4*)&sB[nxt][bk][bo] = bv2;
        }
    }

    #pragma unroll
    for (int i = 0; i < 8; i++) {
        float* orow = out + (size_t)(n0 + 8 * ty + i) * 256 + o0;
        #pragma unroll
        for (int j = 0; j < 4; j++) {
            int c = (j < 2) ? (4 * tx + 2 * j) : (64 + 4 * tx + 2 * (j - 2));
            float lo, hi; unpack2(acc[i][j], lo, hi);
            atomicAdd(&orow[c], lo);
            atomicAdd(&orow[c + 1], hi);
        }
    }
}

// ============================================================
extern "C" void kernel_launch(void* const* d_in, const int* in_sizes, int n_in,
                              void* d_out, int out_size)
{
    const float* q  = (const float*)d_in[0];
    const float* w1 = (const float*)d_in[4];
    const float* b1 = (const float*)d_in[5];
    const float* w2 = (const float*)d_in[6];
    const float* b2 = (const float*)d_in[7];
    const float* lw = (const float*)d_in[8];
    const float* lb = (const float*)d_in[9];
    float* out = (float*)d_out;

    cudaFuncSetAttribute(k_fused, cudaFuncAttributeMaxDynamicSharedMemorySize,
                         SMEMF * 4);
    k_fused<<<NB, 512, SMEMF * 4>>>(q, w1, b1, w2, b2);
    k_bias<<<256, 256>>>(lb, out);
    k_gemm<<<dim3(2, 2, SPLITK), 256>>>(lw, out);
}

// round 8
// speedup vs baseline: 1.1750x; 1.1750x over previous
#include <cuda_runtime.h>
#include <cuda_bf16.h>

typedef unsigned long long ull;

#define NB   256
#define TT   254
#define AUGS 148
#define CH   145
#define SIGK 21170
#define SIGS 21184

__device__ float g_aug[NB * TT * AUGS];
__device__ float g_sig[NB * SIGS];

__device__ __forceinline__ ull pack2(float lo, float hi) {
    ull r; asm("mov.b64 %0, {%1, %2};" : "=l"(r) : "f"(lo), "f"(hi)); return r;
}
__device__ __forceinline__ void unpack2(ull v, float& lo, float& hi) {
    asm("mov.b64 {%0, %1}, %2;" : "=f"(lo), "=f"(hi) : "l"(v));
}
__device__ __forceinline__ void ffma2(ull& acc, ull a, ull b) {
    asm("fma.rn.f32x2 %0, %1, %2, %0;" : "+l"(acc) : "l"(a), "l"(b));
}

// ============================================================
// K1: conv1(3,16->64) + conv2(1x1,64->128,relu) -> g_aug
// ============================================================
#define HS 72
__global__ __launch_bounds__(256, 2) void k_front(
    const float* __restrict__ q,
    const float* __restrict__ w1, const float* __restrict__ b1,
    const float* __restrict__ w2, const float* __restrict__ b2)
{
    extern __shared__ float sm[];
    float* sXd = sm;              // 8192
    float* sW1 = sm + 8192;       // 3072
    float* sW2 = sm + 11264;      // 8192
    float* sH  = sm + 19456;      // 4608
    float* sB1 = sm + 24064;      // 64
    float* sB2 = sm + 24128;      // 128

    int n = blockIdx.x, tid = threadIdx.x;
    int b = n >> 3, hh = n & 7;

    for (int idx = tid; idx < 4096; idx += 256) {
        int t = idx >> 4, e = idx & 15;
        float v = q[(((size_t)b * 256 + t) * 8 + hh) * 16 + e];
        *(ull*)&sXd[2 * idx] = pack2(v, v);
    }
    for (int idx = tid; idx < 3072; idx += 256) sW1[idx] = w1[idx];
    for (int idx = tid; idx < 8192; idx += 256) sW2[idx] = w2[idx];
    if (tid < 64) sB1[tid] = b1[tid];
    else if (tid < 192) sB2[tid - 64] = b2[tid - 64];
    __syncthreads();

    float* aug = g_aug + (size_t)n * (TT * AUGS);

    for (int t = tid >> 5; t < TT; t += 8) {
        for (int c = tid & 31; c < 17; c += 32) {
            aug[t * AUGS + c] = (c < 16) ? sXd[2 * ((t + 2) * 16 + c)]
                                         : (float)t * (1.0f / 253.0f);
        }
    }

    int mg = tid & 7,  tg  = tid >> 3;
    int cg = tid & 15, tgq = tid >> 4;

    for (int t0 = 0; t0 < TT; t0 += 64) {
        int tc = min(64, TT - t0);
        __syncthreads();
        // ---- conv1 ----
        {
            ull acc[2][4];
            #pragma unroll
            for (int j = 0; j < 4; j++) {
                ull bia = pack2(sB1[2 * (mg + 8 * j)], sB1[2 * (mg + 8 * j) + 1]);
                acc[0][j] = bia; acc[1][j] = bia;
            }
            const ull* xr0 = (const ull*)sXd + (t0 + 2 * tg) * 16;
            const ull* xr1 = xr0 + 16;
            #pragma unroll
            for (int we = 0; we < 48; we++) {
                ull xa = xr0[we], xb = xr1[we];
                #pragma unroll
                for (int j = 0; j < 4; j++) {
                    ull wv = *(const ull*)&sW1[we * 64 + 2 * (mg + 8 * j)];
                    ffma2(acc[0][j], xa, wv);
                    ffma2(acc[1][j], xb, wv);
                }
            }
            #pragma unroll
            for (int tl = 0; tl < 2; tl++) {
                int t = 2 * tg + tl;
                if (t < tc) {
                    float* hr = &sH[t * HS];
                    #pragma unroll
                    for (int j = 0; j < 4; j++)
                        *(ull*)&hr[2 * (mg + 8 * j)] = acc[tl][j];
                }
            }
        }
        __syncthreads();
        // ---- conv2 + relu ----
        {
            ull acc[4][4];
            #pragma unroll
            for (int j = 0; j < 4; j++) {
                ull bia = pack2(sB2[2 * (cg + 16 * j)], sB2[2 * (cg + 16 * j) + 1]);
                #pragma unroll
                for (int i = 0; i < 4; i++) acc[i][j] = bia;
            }
            #pragma unroll
            for (int m = 0; m < 64; m++) {
                ull wv[4];
                #pragma unroll
                for (int j = 0; j < 4; j++)
                    wv[j] = *(const ull*)&sW2[m * 128 + 2 * (cg + 16 * j)];
                #pragma unroll
                for (int i = 0; i < 4; i++) {
                    float h = sH[(4 * tgq + i) * HS + m];
                    ull hv = pack2(h, h);
                    #pragma unroll
                    for (int j = 0; j < 4; j++) ffma2(acc[i][j], hv, wv[j]);
                }
            }
            #pragma unroll
            for (int i = 0; i < 4; i++) {
                int t = 4 * tgq + i;
                if (t < tc) {
                    float* ar = aug + (size_t)(t0 + t) * AUGS + 17;
                    #pragma unroll
                    for (int j = 0; j < 4; j++) {
                        float lo, hi; unpack2(acc[i][j], lo, hi);
                        int c = 2 * (cg + 16 * j);
                        ar[c]     = fmaxf(lo, 0.f);
                        ar[c + 1] = fmaxf(hi, 0.f);
                    }
                }
            }
        }
    }
}

// ============================================================
// K2: signature, one CTA per n, 10x5-pair micro-tile (fma-bound)
// per k-step: 5 LDS.64 (D) + 10 LDS.32 (U) + 50 FFMA2
// ============================================================
__global__ __launch_bounds__(256) void k_sig()
{
    __shared__ float sD[2][8][168];
    __shared__ float sU[2][8][168];
    __shared__ float sA0[168];

    int n = blockIdx.x, tid = threadIdx.x;
    const float* aug = g_aug + (size_t)n * (TT * AUGS);
    float* sig = g_sig + (size_t)n * SIGS;

    if (tid < 168) sA0[tid] = (tid < CH) ? aug[tid] : 0.f;
    if (tid < CH) sig[tid] = aug[253 * AUGS + tid] - aug[tid];   // s1
    if (tid >= 192 && tid < 192 + (SIGS - SIGK)) sig[SIGK + (tid - 192)] = 0.f;

    int kk = tid >> 5, cx = tid & 31;   // fill: 8 k-rows x 32 col-threads x 5
    int ty = tid >> 4, tx = tid & 15;   // compute: rows ty+16r, pairs tx+16s

    // prefetch tile 0
    float pa[5], pb[5];
    {
        const float* rr = aug + (size_t)kk * AUGS;
        #pragma unroll
        for (int s = 0; s < 5; s++) {
            int c = cx + 32 * s;
            bool ok = (c < CH);
            pa[s] = ok ? rr[c] : 0.f;
            pb[s] = ok ? rr[AUGS + c] : 0.f;
        }
    }
    __syncthreads();                    // sA0 ready
    #pragma unroll
    for (int s = 0; s < 5; s++) {
        int c = cx + 32 * s;
        sD[0][kk][c] = pb[s] - pa[s];
        sU[0][kk][c] = 0.5f * (pa[s] + pb[s]) - sA0[c];
    }
    __syncthreads();

    ull acc[10][5];
    #pragma unroll
    for (int r = 0; r < 10; r++)
        #pragma unroll
        for (int s = 0; s < 5; s++) acc[r][s] = 0ull;

    for (int it = 0; it < 32; it++) {
        int cur = it & 1;
        float na[5], nb[5];
        if (it + 1 < 32) {
            int t = 8 * (it + 1) + kk;
            bool tok = (t < 253);
            const float* rr = aug + (size_t)(tok ? t : 0) * AUGS;
            #pragma unroll
            for (int s = 0; s < 5; s++) {
                int c = cx + 32 * s;
                bool ok = tok && (c < CH);
                na[s] = ok ? rr[c] : 0.f;
                nb[s] = ok ? rr[AUGS + c] : 0.f;
            }
        }
        #pragma unroll
        for (int k2 = 0; k2 < 8; k2++) {
            ull d2[5];
            #pragma unroll
            for (int s = 0; s < 5; s++)
                d2[s] = *(const ull*)&sD[cur][k2][2 * (tx + 16 * s)];
            #pragma unroll
            for (int r = 0; r < 10; r++) {
                float u = sU[cur][k2][ty + 16 * r];
                ull uu = pack2(u, u);
                #pragma unroll
                for (int s = 0; s < 5; s++) ffma2(acc[r][s], uu, d2[s]);
            }
        }
        if (it + 1 < 32) {
            int nxt = cur ^ 1;
            #pragma unroll
            for (int s = 0; s < 5; s++) {
                int c = cx + 32 * s;
                sD[nxt][kk][c] = nb[s] - na[s];
                sU[nxt][kk][c] = 0.5f * (na[s] + nb[s]) - sA0[c];
            }
        }
        __syncthreads();
    }

    #pragma unroll
    for (int r = 0; r < 10; r++) {
        int i = ty + 16 * r;
        if (i >= CH) continue;
        float* row = sig + 145 + i * 145;
        #pragma unroll
        for (int s = 0; s < 5; s++) {
            int j = 2 * (tx + 16 * s);
            float lo, hi; unpack2(acc[r][s], lo, hi);
            if (j < CH)     row[j]     = lo;
            if (j + 1 < CH) row[j + 1] = hi;
        }
    }
}

// ============================================================
// K3a: init out with bias
// ============================================================
__global__ void k_bias(const float* __restrict__ lb, float* __restrict__ out)
{
    int i = blockIdx.x * 256 + threadIdx.x;
    out[i] = lb[i & 255];
}

// ============================================================
// K3b: split-K GEMM; A non-duplicated (LDS balance 2.0 B/FFMA2)
// ============================================================
#define SPLITK 72
#define KCH    296
#define SAS    132

__global__ __launch_bounds__(256, 2) void k_gemm(
    const float* __restrict__ W, float* __restrict__ out)
{
    __shared__ float sA[2][8][SAS];
    __shared__ float sB[2][8][132];

    int n0 = blockIdx.x * 128, o0 = blockIdx.y * 128;
    int kb = blockIdx.z * KCH;
    int kend = min(kb + KCH, SIGS);
    int nk = (kend - kb) >> 3;
    int tid = threadIdx.x, ty = tid >> 4, tx = tid & 15;

    int am = tid >> 1;
    int ak = (tid & 1) * 4;
    int bk = tid >> 5;
    int bo = (tid & 31) * 4;

    const float* aptr = &g_sig[(size_t)(n0 + am) * SIGS + ak];
    const float* bptr = &W[(size_t)bk * 256 + o0 + bo];

    ull acc[8][4];
    #pragma unroll
    for (int i = 0; i < 8; i++)
        #pragma unroll
        for (int j = 0; j < 4; j++) acc[i][j] = 0ull;

    float4 av = *(const float4*)(aptr + kb);
    float4 bv = make_float4(0.f, 0.f, 0.f, 0.f);
    if (kb + bk < SIGK) bv = *(const float4*)(bptr + (size_t)kb * 256);
    sA[0][ak + 0][am] = av.x; sA[0][ak + 1][am] = av.y;
    sA[0][ak + 2][am] = av.z; sA[0][ak + 3][am] = av.w;
    *(float4*)&sB[0][bk][bo] = bv;

    for (int it = 0; it < nk; it++) {
        int cur = it & 1;
        float4 av2, bv2;
        if (it + 1 < nk) {
            int k0 = kb + 8 * (it + 1);
            av2 = *(const float4*)(aptr + k0);
            bv2 = make_float4(0.f, 0.f, 0.f, 0.f);
            if (k0 + bk < SIGK) bv2 = *(const float4*)(bptr + (size_t)k0 * 256);
        }
        __syncthreads();
        #pragma unroll
        for (int kk = 0; kk < 8; kk++) {
            const float* arow = &sA[cur][kk][8 * ty];
            ull a[8];
            #pragma unroll
            for (int i = 0; i < 8; i++) {
                float v = arow[i];
                a[i] = pack2(v, v);
            }
            ulonglong2 bl = *(const ulonglong2*)&sB[cur][kk][4 * tx];
            ulonglong2 bh = *(const ulonglong2*)&sB[cur][kk][64 + 4 * tx];
            #pragma unroll
            for (int i = 0; i < 8; i++) {
                ffma2(acc[i][0], a[i], bl.x);
                ffma2(acc[i][1], a[i], bl.y);
                ffma2(acc[i][2], a[i], bh.x);
                ffma2(acc[i][3], a[i], bh.y);
            }
        }
        if (it + 1 < nk) {
            int nxt = cur ^ 1;
            sA[nxt][ak + 0][am] = av2.x; sA[nxt][ak + 1][am] = av2.y;
            sA[nxt][ak + 2][am] = av2.z; sA[nxt][ak + 3][am] = av2.w;
            *(float4*)&sB[nxt][bk][bo] = bv2;
        }
    }

    #pragma unroll
    for (int i = 0; i < 8; i++) {
        float* orow = out + (size_t)(n0 + 8 * ty + i) * 256 + o0;
        #pragma unroll
        for (int j = 0; j < 4; j++) {
            int c = (j < 2) ? (4 * tx + 2 * j) : (64 + 4 * tx + 2 * (j - 2));
            float lo, hi; unpack2(acc[i][j], lo, hi);
            atomicAdd(&orow[c], lo);
            atomicAdd(&orow[c + 1], hi);
        }
    }
}

// ============================================================
extern "C" void kernel_launch(void* const* d_in, const int* in_sizes, int n_in,
                              void* d_out, int out_size)
{
    const float* q  = (const float*)d_in[0];
    const float* w1 = (const float*)d_in[4];
    const float* b1 = (const float*)d_in[5];
    const float* w2 = (const float*)d_in[6];
    const float* b2 = (const float*)d_in[7];
    const float* lw = (const float*)d_in[8];
    const float* lb = (const float*)d_in[9];
    float* out = (float*)d_out;

    cudaFuncSetAttribute(k_front, cudaFuncAttributeMaxDynamicSharedMemorySize,
                         24256 * 4);
    k_front<<<NB, 256, 24256 * 4>>>(q, w1, b1, w2, b2);
    k_sig<<<NB, 256>>>();
    k_bias<<<256, 256>>>(lb, out);
    k_gemm<<<dim3(2, 2, SPLITK), 256>>>(lw, out);
}